// round 11
// baseline (speedup 1.0000x reference)
#include <cuda_runtime.h>
#include <cuda_bf16.h>
#include <cuda_fp16.h>
#include <cstdint>

#define NODES 100000
#define EDGES 1600000
#define HID   128

// ---- scratch (static __device__; runtime alloc forbidden) ----
__device__ int    g_is32;
__device__ __align__(16) int g_deg[NODES];   // zeroed by k_agg tail (prev run)
__device__ int    g_cnt[NODES];
__device__ float  g_dinv[NODES];
__device__ int    g_rowptr[NODES + 1];
__device__ int    g_csr[EDGES];
__device__ __align__(16) __half g_xsh[(size_t)NODES * HID];  // (x@W)*dinv fp16
__device__ __align__(16) __nv_bfloat16 g_wh[128 * 128];      // W hi bf16 [k][n]
__device__ __align__(16) __nv_bfloat16 g_wl[128 * 128];      // W lo bf16

// ------------------------------------------------- W prep: bf16 hi/lo
__global__ void k_prep_w(const float* __restrict__ W) {
    int idx = blockIdx.x * blockDim.x + threadIdx.x;
    if (idx >= 128 * 128) return;
    float v = W[idx];
    __nv_bfloat16 hi = __float2bfloat16(v);
    g_wh[idx] = hi;
    g_wl[idx] = __float2bfloat16(v - __bfloat162float(hi));
}

// ------------------------------------------------- dtype detect (1 warp)
__global__ void k_detect(const void* ei, int E, int N) {
    const long long* e64 = (const long long*)ei;
    int lane = threadIdx.x, bad = 0;
    int limit = E < 1024 ? E : 1024;
    for (int j = lane; j < limit; j += 32) {
        long long v = e64[j];
        if (v < 0 || v >= (long long)N) bad = 1;
    }
    unsigned m = __ballot_sync(0xffffffffu, bad);
    if (lane == 0) g_is32 = (m != 0u) ? 1 : 0;
}

__device__ __forceinline__ int load_idx(const void* ei, size_t pos, int is32) {
    if (is32) return ((const int*)ei)[pos];
    return (int)((const long long*)ei)[pos];
}

__global__ void k_count(const void* __restrict__ ei, int E) {
    int is32 = g_is32;
    int i = blockIdx.x * blockDim.x + threadIdx.x;
    int stride = gridDim.x * blockDim.x;
    for (; i < E; i += stride) {
        int d = load_idx(ei, (size_t)E + i, is32);
        atomicAdd(&g_deg[d], 1);
    }
}

// -------------------------- single-block chained scan: dinv+rowptr+cnt
__global__ void __launch_bounds__(1024) k_scan(int N) {
    __shared__ int warp_sums[32];
    __shared__ int carry_s;
    int tid = threadIdx.x, lane = tid & 31, wid = tid >> 5;
    if (tid == 0) carry_s = 0;
    __syncthreads();

    for (int base = 0; base < N; base += 4096) {
        int idx = base + tid * 4;
        int4 d = make_int4(0, 0, 0, 0);
        if (idx + 3 < N) {
            d = *(const int4*)&g_deg[idx];
        } else {
            if (idx + 0 < N) d.x = g_deg[idx + 0];
            if (idx + 1 < N) d.y = g_deg[idx + 1];
            if (idx + 2 < N) d.z = g_deg[idx + 2];
            if (idx + 3 < N) d.w = g_deg[idx + 3];
        }
        int tsum = d.x + d.y + d.z + d.w;
        int inc = tsum;
#pragma unroll
        for (int off = 1; off < 32; off <<= 1) {
            int u = __shfl_up_sync(0xffffffffu, inc, off);
            if (lane >= off) inc += u;
        }
        if (lane == 31) warp_sums[wid] = inc;
        __syncthreads();
        if (wid == 0) {
            int wv = warp_sums[lane];
#pragma unroll
            for (int off = 1; off < 32; off <<= 1) {
                int u = __shfl_up_sync(0xffffffffu, wv, off);
                if (lane >= off) wv += u;
            }
            warp_sums[lane] = wv;           // inclusive warp prefix
        }
        __syncthreads();
        int excl = inc - tsum + (wid ? warp_sums[wid - 1] : 0) + carry_s;
        int dd[4] = {d.x, d.y, d.z, d.w};
        int p = 0;
#pragma unroll
        for (int j = 0; j < 4; j++) {
            int ix = idx + j;
            if (ix < N) {
                int r = excl + p;
                g_rowptr[ix] = r;
                g_cnt[ix] = r;
                g_dinv[ix] = rsqrtf((float)(dd[j] + 1));   // +1 self loop
            }
            p += dd[j];
        }
        __syncthreads();
        if (tid == 0) carry_s += warp_sums[31];
        __syncthreads();
    }
    if (tid == 0) g_rowptr[N] = carry_s;
}

// CSR fill: single atomic per edge (cnt pre-seeded with rowptr)
__global__ void k_fill(const void* __restrict__ ei, int E) {
    int is32 = g_is32;
    int i = blockIdx.x * blockDim.x + threadIdx.x;
    int stride = gridDim.x * blockDim.x;
    for (; i < E; i += stride) {
        int s = load_idx(ei, i, is32);
        int d = load_idx(ei, (size_t)E + i, is32);
        int p = atomicAdd(&g_cnt[d], 1);
        g_csr[p] = s;
    }
}

// =================================================================== GEMM
// xs = (x @ W) * dinv[row] via mma.sync m16n8k16 bf16x3 (hi/lo split), fp16 out.
#define ST      136                   // bf16 stride per row (conflict-free ldmatrix)
#define ABYTES  (128 * ST * 2)        // 34816 per array
#define SA_HI   0
#define SA_LO   (SA_HI + ABYTES)
#define SB_HI   (SA_LO + ABYTES)
#define SB_LO   (SB_HI + ABYTES)
#define SM_TOTAL (SB_LO + ABYTES)     // 139264

__device__ __forceinline__ void ldsm4(uint32_t& r0, uint32_t& r1, uint32_t& r2,
                                      uint32_t& r3, uint32_t addr) {
    asm volatile("ldmatrix.sync.aligned.m8n8.x4.shared.b16 {%0,%1,%2,%3}, [%4];"
                 : "=r"(r0), "=r"(r1), "=r"(r2), "=r"(r3) : "r"(addr));
}
__device__ __forceinline__ void ldsm4t(uint32_t& r0, uint32_t& r1, uint32_t& r2,
                                       uint32_t& r3, uint32_t addr) {
    asm volatile("ldmatrix.sync.aligned.m8n8.x4.trans.shared.b16 {%0,%1,%2,%3}, [%4];"
                 : "=r"(r0), "=r"(r1), "=r"(r2), "=r"(r3) : "r"(addr));
}
__device__ __forceinline__ void mma16816(float* c, const uint32_t* a, uint32_t b0,
                                         uint32_t b1) {
    asm volatile(
        "mma.sync.aligned.m16n8k16.row.col.f32.bf16.bf16.f32 "
        "{%0,%1,%2,%3}, {%4,%5,%6,%7}, {%8,%9}, {%0,%1,%2,%3};"
        : "+f"(c[0]), "+f"(c[1]), "+f"(c[2]), "+f"(c[3])
        : "r"(a[0]), "r"(a[1]), "r"(a[2]), "r"(a[3]), "r"(b0), "r"(b1));
}

__global__ void __launch_bounds__(256) k_gemm(const float* __restrict__ x, int N) {
    extern __shared__ char smem[];
    uint32_t sb = (uint32_t)__cvta_generic_to_shared(smem);

    int tid = threadIdx.x;
    int wid = tid >> 5;
    int lane = tid & 31;
    int row0 = blockIdx.x * 128;

    {
        const uint4* wh = (const uint4*)g_wh;
        const uint4* wl = (const uint4*)g_wl;
#pragma unroll
        for (int g = 0; g < 8; g++) {
            int i = tid + 256 * g;
            int r = i >> 4, c8 = i & 15;
            uint32_t off = r * (ST * 2) + c8 * 16;
            *(uint4*)(smem + SB_HI + off) = wh[i];
            *(uint4*)(smem + SB_LO + off) = wl[i];
        }
    }

#pragma unroll
    for (int g = 0; g < 8; g++) {
        int i = tid + 256 * g;
        int m = i >> 4, c8 = i & 15;
        int gm = row0 + m;
        float4 v0 = make_float4(0.f, 0.f, 0.f, 0.f), v1 = v0;
        if (gm < N) {
            const float4* p = (const float4*)(x + (size_t)gm * 128 + c8 * 8);
            v0 = p[0]; v1 = p[1];
        }
        float f[8] = {v0.x, v0.y, v0.z, v0.w, v1.x, v1.y, v1.z, v1.w};
        alignas(16) __nv_bfloat16 hh[8];
        alignas(16) __nv_bfloat16 ll[8];
#pragma unroll
        for (int j = 0; j < 8; j++) {
            __nv_bfloat16 hi = __float2bfloat16(f[j]);
            hh[j] = hi;
            ll[j] = __float2bfloat16(f[j] - __bfloat162float(hi));
        }
        uint32_t off = m * (ST * 2) + c8 * 16;
        *(uint4*)(smem + SA_HI + off) = *(uint4*)hh;
        *(uint4*)(smem + SA_LO + off) = *(uint4*)ll;
    }
    __syncthreads();

    int mg = wid >> 1;
    int ng = wid & 1;

    float c[2][8][4];
#pragma unroll
    for (int mi = 0; mi < 2; mi++)
#pragma unroll
        for (int n8 = 0; n8 < 8; n8++)
#pragma unroll
            for (int q = 0; q < 4; q++) c[mi][n8][q] = 0.f;

    int a_row = (lane & 7) + ((lane >> 3) & 1) * 8;
    int a_k   = ((lane >> 4) & 1) * 8;
    int b_k   = (lane & 7) + ((lane >> 3) & 1) * 8;
    int b_n   = ((lane >> 4) & 1) * 8;

    const uint32_t aBase[3] = {sb + SA_HI, sb + SA_LO, sb + SA_HI};
    const uint32_t bBase[3] = {sb + SB_HI, sb + SB_HI, sb + SB_LO};

#pragma unroll
    for (int pass = 0; pass < 3; pass++) {
        uint32_t AB = aBase[pass], BB = bBase[pass];
#pragma unroll
        for (int ks = 0; ks < 8; ks++) {
            int k0 = ks * 16;
            uint32_t a[2][4];
#pragma unroll
            for (int mi = 0; mi < 2; mi++) {
                int r = mg * 32 + mi * 16 + a_row;
                ldsm4(a[mi][0], a[mi][1], a[mi][2], a[mi][3],
                      AB + r * (ST * 2) + (k0 + a_k) * 2);
            }
            uint32_t b[4][4];
#pragma unroll
            for (int j = 0; j < 4; j++) {
                int n0 = ng * 64 + j * 16;
                ldsm4t(b[j][0], b[j][1], b[j][2], b[j][3],
                       BB + (k0 + b_k) * (ST * 2) + (n0 + b_n) * 2);
            }
#pragma unroll
            for (int mi = 0; mi < 2; mi++)
#pragma unroll
                for (int j = 0; j < 4; j++) {
                    mma16816(c[mi][2 * j],     a[mi], b[j][0], b[j][1]);
                    mma16816(c[mi][2 * j + 1], a[mi], b[j][2], b[j][3]);
                }
        }
    }

    // ---- epilogue: scale by dinv, store fp16 ----
#pragma unroll
    for (int mi = 0; mi < 2; mi++) {
        int r0 = mg * 32 + mi * 16 + (lane >> 2);
        int r1 = r0 + 8;
        int gm0 = row0 + r0, gm1 = row0 + r1;
        float d0 = (gm0 < N) ? g_dinv[gm0] : 0.f;
        float d1 = (gm1 < N) ? g_dinv[gm1] : 0.f;
#pragma unroll
        for (int n8 = 0; n8 < 8; n8++) {
            int col = ng * 64 + n8 * 8 + (lane & 3) * 2;
            if (gm0 < N) {
                __half2 h = __floats2half2_rn(d0 * c[mi][n8][0], d0 * c[mi][n8][1]);
                *(__half2*)(g_xsh + (size_t)gm0 * 128 + col) = h;
            }
            if (gm1 < N) {
                __half2 h = __floats2half2_rn(d1 * c[mi][n8][2], d1 * c[mi][n8][3]);
                *(__half2*)(g_xsh + (size_t)gm1 * 128 + col) = h;
            }
        }
    }
}

// ---------------------------------------------- aggregation: one warp / node
// fp16 gather (8B per lane per edge), 2-way unrolled (R5-proven), fp32 accum.
// Also zeroes g_deg for the next graph replay (prologue).
__global__ void __launch_bounds__(256) k_agg(const float* __restrict__ b,
                                             float* __restrict__ out, int N) {
    int t = blockIdx.x * blockDim.x + threadIdx.x;
    if (t < N) g_deg[t] = 0;                  // reset for next run

    int gw = t >> 5;
    int lane = threadIdx.x & 31;
    if (gw >= N) return;

    const uint2* xsv = (const uint2*)g_xsh;   // 8B = 4 halves per lane

    float a0, a1, a2, a3;
    {
        uint2 v = xsv[(size_t)gw * 32 + lane];
        float2 f01 = __half22float2(*(__half2*)&v.x);
        float2 f23 = __half22float2(*(__half2*)&v.y);
        a0 = f01.x; a1 = f01.y; a2 = f23.x; a3 = f23.y;
    }
    float c0 = 0.f, c1 = 0.f, c2 = 0.f, c3 = 0.f;

    int s = g_rowptr[gw], e = g_rowptr[gw + 1];
    int i = s;
    for (; i + 2 <= e; i += 2) {
        int s0 = g_csr[i];
        int s1 = g_csr[i + 1];
        uint2 v0 = xsv[(size_t)s0 * 32 + lane];
        uint2 v1 = xsv[(size_t)s1 * 32 + lane];
        float2 p01 = __half22float2(*(__half2*)&v0.x);
        float2 p23 = __half22float2(*(__half2*)&v0.y);
        float2 q01 = __half22float2(*(__half2*)&v1.x);
        float2 q23 = __half22float2(*(__half2*)&v1.y);
        a0 += p01.x; a1 += p01.y; a2 += p23.x; a3 += p23.y;
        c0 += q01.x; c1 += q01.y; c2 += q23.x; c3 += q23.y;
    }
    if (i < e) {
        int s0 = g_csr[i];
        uint2 v0 = xsv[(size_t)s0 * 32 + lane];
        float2 p01 = __half22float2(*(__half2*)&v0.x);
        float2 p23 = __half22float2(*(__half2*)&v0.y);
        a0 += p01.x; a1 += p01.y; a2 += p23.x; a3 += p23.y;
    }
    a0 += c0; a1 += c1; a2 += c2; a3 += c3;

    float dn = g_dinv[gw];
    float4 bb = ((const float4*)b)[lane];
    float4 o;
    o.x = fmaxf(fmaf(dn, a0, bb.x), 0.f);
    o.y = fmaxf(fmaf(dn, a1, bb.y), 0.f);
    o.z = fmaxf(fmaf(dn, a2, bb.z), 0.f);
    o.w = fmaxf(fmaf(dn, a3, bb.w), 0.f);
    ((float4*)out)[(size_t)gw * 32 + lane] = o;
}

// ---------------------------------------------------------------- launcher
extern "C" void kernel_launch(void* const* d_in, const int* in_sizes, int n_in,
                              void* d_out, int out_size) {
    const float* x  = (const float*)d_in[0];
    const void*  ei = d_in[1];                 // int32 or int64, auto-detected
    const float* W  = (const float*)d_in[2];
    const float* b  = (const float*)d_in[3];
    float* out      = (float*)d_out;

    int N = in_sizes[0] / HID;     // 100000
    int E = in_sizes[1] / 2;       // 1600000

    static cudaStream_t s1;
    static cudaEvent_t ev0, ev_dinv, ev_gemm;
    static int inited = 0;
    if (!inited) {
        cudaFuncSetAttribute(k_gemm, cudaFuncAttributeMaxDynamicSharedMemorySize,
                             SM_TOTAL);
        cudaStreamCreateWithFlags(&s1, cudaStreamNonBlocking);
        cudaEventCreateWithFlags(&ev0, cudaEventDisableTiming);
        cudaEventCreateWithFlags(&ev_dinv, cudaEventDisableTiming);
        cudaEventCreateWithFlags(&ev_gemm, cudaEventDisableTiming);
        inited = 1;
    }

    // side stream joins capture and runs prep_w (no deps)
    cudaEventRecord(ev0, 0);
    cudaStreamWaitEvent(s1, ev0, 0);
    k_prep_w<<<64, 256, 0, s1>>>(W);

    // main chain: detect -> degree count -> fused scan (dinv/rowptr/cnt)
    k_detect<<<1, 32>>>(ei, E, N);
    k_count<<<(E + 255) / 256, 256>>>(ei, E);
    k_scan<<<1, 1024>>>(N);
    cudaEventRecord(ev_dinv, 0);

    // side: GEMM (needs dinv in epilogue) overlaps fill
    cudaStreamWaitEvent(s1, ev_dinv, 0);
    k_gemm<<<(N + 127) / 128, 256, SM_TOTAL, s1>>>(x, N);
    cudaEventRecord(ev_gemm, s1);

    // main: CSR fill
    k_fill<<<(E + 255) / 256, 256>>>(ei, E);

    // join, aggregate
    cudaStreamWaitEvent(0, ev_gemm, 0);
    k_agg<<<(N * 32 + 255) / 256, 256>>>(b, out, N);
}

// round 12
// speedup vs baseline: 1.6863x; 1.6863x over previous
#include <cuda_runtime.h>
#include <cuda_bf16.h>
#include <cuda_fp16.h>
#include <cstdint>

#define NODES 100000
#define EDGES 1600000
#define HID   128

// ---- scratch (static __device__; runtime alloc forbidden) ----
__device__ int    g_is32;
__device__ int    g_deg[NODES];      // zero-init; k_agg re-zeroes for next replay
__device__ int    g_cnt[NODES];
__device__ float  g_dinv[NODES];
__device__ int    g_rowptr[NODES + 1];
__device__ int    g_tilesum[128];
__device__ int    g_tileoff[128];
__device__ int    g_csr[EDGES];
__device__ __align__(16) __half g_xsh[(size_t)NODES * HID];  // (x@W)*dinv fp16
__device__ __align__(16) __nv_bfloat16 g_wh[128 * 128];      // W hi bf16 [k][n]
__device__ __align__(16) __nv_bfloat16 g_wl[128 * 128];      // W lo bf16

// ------------------------------------------------- W prep: bf16 hi/lo
__global__ void k_prep_w(const float* __restrict__ W) {
    int idx = blockIdx.x * blockDim.x + threadIdx.x;
    if (idx >= 128 * 128) return;
    float v = W[idx];
    __nv_bfloat16 hi = __float2bfloat16(v);
    g_wh[idx] = hi;
    g_wl[idx] = __float2bfloat16(v - __bfloat162float(hi));
}

// ------------------------------------------------- dtype detect (1 warp)
__global__ void k_detect(const void* ei, int E, int N) {
    const long long* e64 = (const long long*)ei;
    int lane = threadIdx.x, bad = 0;
    int limit = E < 1024 ? E : 1024;
    for (int j = lane; j < limit; j += 32) {
        long long v = e64[j];
        if (v < 0 || v >= (long long)N) bad = 1;
    }
    unsigned m = __ballot_sync(0xffffffffu, bad);
    if (lane == 0) g_is32 = (m != 0u) ? 1 : 0;
}

__device__ __forceinline__ int load_idx(const void* ei, size_t pos, int is32) {
    if (is32) return ((const int*)ei)[pos];
    return (int)((const long long*)ei)[pos];
}

__global__ void k_count(const void* __restrict__ ei, int E) {
    int is32 = g_is32;
    int i = blockIdx.x * blockDim.x + threadIdx.x;
    int stride = gridDim.x * blockDim.x;
    for (; i < E; i += stride) {
        int d = load_idx(ei, (size_t)E + i, is32);
        atomicAdd(&g_deg[d], 1);
    }
}

// ------------------------------------------------------------- 3-pass scan
__global__ void k_scan1(int N) {
    int base = blockIdx.x * 1024 + threadIdx.x * 4;
    int s = 0;
#pragma unroll
    for (int j = 0; j < 4; j++) {
        int idx = base + j;
        if (idx < N) {
            int d = g_deg[idx];
            s += d;
            g_dinv[idx] = rsqrtf((float)(d + 1));     // +1 self loop
        }
    }
#pragma unroll
    for (int off = 16; off; off >>= 1) s += __shfl_down_sync(0xffffffffu, s, off);
    __shared__ int sm[8];
    int lane = threadIdx.x & 31, wid = threadIdx.x >> 5;
    if (lane == 0) sm[wid] = s;
    __syncthreads();
    if (wid == 0) {
        s = (lane < 8) ? sm[lane] : 0;
#pragma unroll
        for (int off = 4; off; off >>= 1) s += __shfl_down_sync(0xffffffffu, s, off);
        if (lane == 0) g_tilesum[blockIdx.x] = s;
    }
}

__global__ void k_scan2(int NT, int N) {
    __shared__ int sm[128];
    int t = threadIdx.x;
    int v = (t < NT) ? g_tilesum[t] : 0;
    sm[t] = v;
    __syncthreads();
    for (int off = 1; off < 128; off <<= 1) {
        int u = (t >= off) ? sm[t - off] : 0;
        __syncthreads();
        sm[t] += u;
        __syncthreads();
    }
    if (t < NT) g_tileoff[t] = sm[t] - v;
    if (t == 127) g_rowptr[N] = sm[127];
}

// scan3: writes rowptr AND pre-seeds g_cnt = rowptr (fill slot counters)
__global__ void k_scan3(int N) {
    int t = threadIdx.x;
    int base = blockIdx.x * 1024 + t * 4;
    int d[4];
#pragma unroll
    for (int j = 0; j < 4; j++) {
        int idx = base + j;
        d[j] = (idx < N) ? g_deg[idx] : 0;
    }
    int tsum = d[0] + d[1] + d[2] + d[3];
    int lane = t & 31, wid = t >> 5;
    int inc = tsum;
#pragma unroll
    for (int off = 1; off < 32; off <<= 1) {
        int u = __shfl_up_sync(0xffffffffu, inc, off);
        if (lane >= off) inc += u;
    }
    __shared__ int ws[8];
    if (lane == 31) ws[wid] = inc;
    __syncthreads();
    if (wid == 0 && lane < 8) {
        int wv = ws[lane];
#pragma unroll
        for (int off = 1; off < 8; off <<= 1) {
            int u = __shfl_up_sync(0x000000ffu, wv, off);
            if (lane >= off) wv += u;
        }
        ws[lane] = wv;
    }
    __syncthreads();
    int excl = inc - tsum + (wid ? ws[wid - 1] : 0) + g_tileoff[blockIdx.x];
    int p = 0;
#pragma unroll
    for (int j = 0; j < 4; j++) {
        int idx = base + j;
        if (idx < N) {
            g_rowptr[idx] = excl + p;
            g_cnt[idx] = excl + p;       // seed fill counter
        }
        p += d[j];
    }
}

// CSR fill: single atomic per edge (cnt pre-seeded with rowptr)
__global__ void k_fill(const void* __restrict__ ei, int E) {
    int is32 = g_is32;
    int i = blockIdx.x * blockDim.x + threadIdx.x;
    int stride = gridDim.x * blockDim.x;
    for (; i < E; i += stride) {
        int s = load_idx(ei, i, is32);
        int d = load_idx(ei, (size_t)E + i, is32);
        int p = atomicAdd(&g_cnt[d], 1);
        g_csr[p] = s;
    }
}

// =================================================================== GEMM
// xs = (x @ W) * dinv[row] via mma.sync m16n8k16 bf16x3 (hi/lo split), fp16 out.
#define ST      136                   // bf16 stride per row (conflict-free ldmatrix)
#define ABYTES  (128 * ST * 2)        // 34816 per array
#define SA_HI   0
#define SA_LO   (SA_HI + ABYTES)
#define SB_HI   (SA_LO + ABYTES)
#define SB_LO   (SB_HI + ABYTES)
#define SM_TOTAL (SB_LO + ABYTES)     // 139264

__device__ __forceinline__ void ldsm4(uint32_t& r0, uint32_t& r1, uint32_t& r2,
                                      uint32_t& r3, uint32_t addr) {
    asm volatile("ldmatrix.sync.aligned.m8n8.x4.shared.b16 {%0,%1,%2,%3}, [%4];"
                 : "=r"(r0), "=r"(r1), "=r"(r2), "=r"(r3) : "r"(addr));
}
__device__ __forceinline__ void ldsm4t(uint32_t& r0, uint32_t& r1, uint32_t& r2,
                                       uint32_t& r3, uint32_t addr) {
    asm volatile("ldmatrix.sync.aligned.m8n8.x4.trans.shared.b16 {%0,%1,%2,%3}, [%4];"
                 : "=r"(r0), "=r"(r1), "=r"(r2), "=r"(r3) : "r"(addr));
}
__device__ __forceinline__ void mma16816(float* c, const uint32_t* a, uint32_t b0,
                                         uint32_t b1) {
    asm volatile(
        "mma.sync.aligned.m16n8k16.row.col.f32.bf16.bf16.f32 "
        "{%0,%1,%2,%3}, {%4,%5,%6,%7}, {%8,%9}, {%0,%1,%2,%3};"
        : "+f"(c[0]), "+f"(c[1]), "+f"(c[2]), "+f"(c[3])
        : "r"(a[0]), "r"(a[1]), "r"(a[2]), "r"(a[3]), "r"(b0), "r"(b1));
}

__global__ void __launch_bounds__(256) k_gemm(const float* __restrict__ x, int N) {
    extern __shared__ char smem[];
    uint32_t sb = (uint32_t)__cvta_generic_to_shared(smem);

    int tid = threadIdx.x;
    int wid = tid >> 5;
    int lane = tid & 31;
    int row0 = blockIdx.x * 128;

    {
        const uint4* wh = (const uint4*)g_wh;
        const uint4* wl = (const uint4*)g_wl;
#pragma unroll
        for (int g = 0; g < 8; g++) {
            int i = tid + 256 * g;
            int r = i >> 4, c8 = i & 15;
            uint32_t off = r * (ST * 2) + c8 * 16;
            *(uint4*)(smem + SB_HI + off) = wh[i];
            *(uint4*)(smem + SB_LO + off) = wl[i];
        }
    }

#pragma unroll
    for (int g = 0; g < 8; g++) {
        int i = tid + 256 * g;
        int m = i >> 4, c8 = i & 15;
        int gm = row0 + m;
        float4 v0 = make_float4(0.f, 0.f, 0.f, 0.f), v1 = v0;
        if (gm < N) {
            const float4* p = (const float4*)(x + (size_t)gm * 128 + c8 * 8);
            v0 = p[0]; v1 = p[1];
        }
        float f[8] = {v0.x, v0.y, v0.z, v0.w, v1.x, v1.y, v1.z, v1.w};
        alignas(16) __nv_bfloat16 hh[8];
        alignas(16) __nv_bfloat16 ll[8];
#pragma unroll
        for (int j = 0; j < 8; j++) {
            __nv_bfloat16 hi = __float2bfloat16(f[j]);
            hh[j] = hi;
            ll[j] = __float2bfloat16(f[j] - __bfloat162float(hi));
        }
        uint32_t off = m * (ST * 2) + c8 * 16;
        *(uint4*)(smem + SA_HI + off) = *(uint4*)hh;
        *(uint4*)(smem + SA_LO + off) = *(uint4*)ll;
    }
    __syncthreads();

    int mg = wid >> 1;
    int ng = wid & 1;

    float c[2][8][4];
#pragma unroll
    for (int mi = 0; mi < 2; mi++)
#pragma unroll
        for (int n8 = 0; n8 < 8; n8++)
#pragma unroll
            for (int q = 0; q < 4; q++) c[mi][n8][q] = 0.f;

    int a_row = (lane & 7) + ((lane >> 3) & 1) * 8;
    int a_k   = ((lane >> 4) & 1) * 8;
    int b_k   = (lane & 7) + ((lane >> 3) & 1) * 8;
    int b_n   = ((lane >> 4) & 1) * 8;

    const uint32_t aBase[3] = {sb + SA_HI, sb + SA_LO, sb + SA_HI};
    const uint32_t bBase[3] = {sb + SB_HI, sb + SB_HI, sb + SB_LO};

#pragma unroll
    for (int pass = 0; pass < 3; pass++) {
        uint32_t AB = aBase[pass], BB = bBase[pass];
#pragma unroll
        for (int ks = 0; ks < 8; ks++) {
            int k0 = ks * 16;
            uint32_t a[2][4];
#pragma unroll
            for (int mi = 0; mi < 2; mi++) {
                int r = mg * 32 + mi * 16 + a_row;
                ldsm4(a[mi][0], a[mi][1], a[mi][2], a[mi][3],
                      AB + r * (ST * 2) + (k0 + a_k) * 2);
            }
            uint32_t b[4][4];
#pragma unroll
            for (int j = 0; j < 4; j++) {
                int n0 = ng * 64 + j * 16;
                ldsm4t(b[j][0], b[j][1], b[j][2], b[j][3],
                       BB + (k0 + b_k) * (ST * 2) + (n0 + b_n) * 2);
            }
#pragma unroll
            for (int mi = 0; mi < 2; mi++)
#pragma unroll
                for (int j = 0; j < 4; j++) {
                    mma16816(c[mi][2 * j],     a[mi], b[j][0], b[j][1]);
                    mma16816(c[mi][2 * j + 1], a[mi], b[j][2], b[j][3]);
                }
        }
    }

    // ---- epilogue: scale by dinv, store fp16 ----
#pragma unroll
    for (int mi = 0; mi < 2; mi++) {
        int r0 = mg * 32 + mi * 16 + (lane >> 2);
        int r1 = r0 + 8;
        int gm0 = row0 + r0, gm1 = row0 + r1;
        float d0 = (gm0 < N) ? g_dinv[gm0] : 0.f;
        float d1 = (gm1 < N) ? g_dinv[gm1] : 0.f;
#pragma unroll
        for (int n8 = 0; n8 < 8; n8++) {
            int col = ng * 64 + n8 * 8 + (lane & 3) * 2;
            if (gm0 < N) {
                __half2 h = __floats2half2_rn(d0 * c[mi][n8][0], d0 * c[mi][n8][1]);
                *(__half2*)(g_xsh + (size_t)gm0 * 128 + col) = h;
            }
            if (gm1 < N) {
                __half2 h = __floats2half2_rn(d1 * c[mi][n8][2], d1 * c[mi][n8][3]);
                *(__half2*)(g_xsh + (size_t)gm1 * 128 + col) = h;
            }
        }
    }
}

// ---------------------------------------------- aggregation: one warp / node
// fp16 gather (8B per lane per edge), 2-way unrolled, fp32 accum.
// Prologue re-zeroes g_deg for the next graph replay.
__global__ void __launch_bounds__(256) k_agg(const float* __restrict__ b,
                                             float* __restrict__ out, int N) {
    int t = blockIdx.x * blockDim.x + threadIdx.x;
    if (t < N) g_deg[t] = 0;                  // reset for next replay

    int gw = t >> 5;
    int lane = threadIdx.x & 31;
    if (gw >= N) return;

    const uint2* xsv = (const uint2*)g_xsh;   // 8B = 4 halves per lane

    float a0, a1, a2, a3;
    {
        uint2 v = xsv[(size_t)gw * 32 + lane];
        float2 f01 = __half22float2(*(__half2*)&v.x);
        float2 f23 = __half22float2(*(__half2*)&v.y);
        a0 = f01.x; a1 = f01.y; a2 = f23.x; a3 = f23.y;
    }
    float c0 = 0.f, c1 = 0.f, c2 = 0.f, c3 = 0.f;

    int s = g_rowptr[gw], e = g_rowptr[gw + 1];
    int i = s;
    for (; i + 2 <= e; i += 2) {
        int s0 = g_csr[i];
        int s1 = g_csr[i + 1];
        uint2 v0 = xsv[(size_t)s0 * 32 + lane];
        uint2 v1 = xsv[(size_t)s1 * 32 + lane];
        float2 p01 = __half22float2(*(__half2*)&v0.x);
        float2 p23 = __half22float2(*(__half2*)&v0.y);
        float2 q01 = __half22float2(*(__half2*)&v1.x);
        float2 q23 = __half22float2(*(__half2*)&v1.y);
        a0 += p01.x; a1 += p01.y; a2 += p23.x; a3 += p23.y;
        c0 += q01.x; c1 += q01.y; c2 += q23.x; c3 += q23.y;
    }
    if (i < e) {
        int s0 = g_csr[i];
        uint2 v0 = xsv[(size_t)s0 * 32 + lane];
        float2 p01 = __half22float2(*(__half2*)&v0.x);
        float2 p23 = __half22float2(*(__half2*)&v0.y);
        a0 += p01.x; a1 += p01.y; a2 += p23.x; a3 += p23.y;
    }
    a0 += c0; a1 += c1; a2 += c2; a3 += c3;

    float dn = g_dinv[gw];
    float4 bb = ((const float4*)b)[lane];
    float4 o;
    o.x = fmaxf(fmaf(dn, a0, bb.x), 0.f);
    o.y = fmaxf(fmaf(dn, a1, bb.y), 0.f);
    o.z = fmaxf(fmaf(dn, a2, bb.z), 0.f);
    o.w = fmaxf(fmaf(dn, a3, bb.w), 0.f);
    ((float4*)out)[(size_t)gw * 32 + lane] = o;
}

// ---------------------------------------------------------------- launcher
extern "C" void kernel_launch(void* const* d_in, const int* in_sizes, int n_in,
                              void* d_out, int out_size) {
    const float* x  = (const float*)d_in[0];
    const void*  ei = d_in[1];                 // int32 or int64, auto-detected
    const float* W  = (const float*)d_in[2];
    const float* b  = (const float*)d_in[3];
    float* out      = (float*)d_out;

    int N = in_sizes[0] / HID;     // 100000
    int E = in_sizes[1] / 2;       // 1600000
    int NT = (N + 1023) / 1024;

    static cudaStream_t s1;
    static cudaEvent_t ev0, ev_dinv, ev_gemm;
    static int inited = 0;
    if (!inited) {
        cudaFuncSetAttribute(k_gemm, cudaFuncAttributeMaxDynamicSharedMemorySize,
                             SM_TOTAL);
        cudaStreamCreateWithFlags(&s1, cudaStreamNonBlocking);
        cudaEventCreateWithFlags(&ev0, cudaEventDisableTiming);
        cudaEventCreateWithFlags(&ev_dinv, cudaEventDisableTiming);
        cudaEventCreateWithFlags(&ev_gemm, cudaEventDisableTiming);
        inited = 1;
    }

    // side stream joins capture and runs prep_w (no deps)
    cudaEventRecord(ev0, 0);
    cudaStreamWaitEvent(s1, ev0, 0);
    k_prep_w<<<64, 256, 0, s1>>>(W);

    // main chain: detect -> degree count -> dinv
    k_detect<<<1, 32>>>(ei, E, N);
    k_count<<<(E + 255) / 256, 256>>>(ei, E);
    k_scan1<<<NT, 256>>>(N);
    cudaEventRecord(ev_dinv, 0);

    // side: GEMM (needs dinv in epilogue) overlaps scan2/scan3/fill
    cudaStreamWaitEvent(s1, ev_dinv, 0);
    k_gemm<<<(N + 127) / 128, 256, SM_TOTAL, s1>>>(x, N);
    cudaEventRecord(ev_gemm, s1);

    // main: finish CSR build
    k_scan2<<<1, 128>>>(NT, N);
    k_scan3<<<NT, 256>>>(N);
    k_fill<<<(E + 255) / 256, 256>>>(ei, E);

    // join, aggregate
    cudaStreamWaitEvent(0, ev_gemm, 0);
    k_agg<<<(N * 32 + 255) / 256, 256>>>(b, out, N);
}